// round 3
// baseline (speedup 1.0000x reference)
#include <cuda_runtime.h>
#include <cstdint>
#include <cstddef>

#define NN   100000
#define IND  512
#define HIDD 256
#define OUTD 64

// Scratch (device globals: allocation-free, graph-capture safe). ~256 MB.
__device__ float g_sup1[(size_t)NN * HIDD];  // x @ W1
__device__ float g_h   [(size_t)NN * HIDD];  // spmm1 accum
__device__ float g_sup2[(size_t)NN * OUTD];  // relu(h) @ W2
__device__ float g_o2  [(size_t)NN * OUTD];  // spmm2 accum

// ---------------------------------------------------------------------------
// Tiled fp32 GEMM: C[M,N] = A[M,K] @ B[K,N], row-major. BM=BN=64, BK=32,
// 256 threads, 4x4 micro-tile per thread. Optional ReLU applied to A reads.
// Only the M dimension needs bounds guards (K, N divide evenly here).
// ---------------------------------------------------------------------------
template <bool RELU>
__global__ __launch_bounds__(256) void gemm64(const float* __restrict__ A,
                                              const float* __restrict__ B,
                                              float* __restrict__ C,
                                              int M, int N, int K) {
    __shared__ __align__(16) float As[32][68];  // [k][m], 68 = pad (272B row, 16B aligned)
    __shared__ __align__(16) float Bs[32][68];  // [k][n]

    const int tid = threadIdx.x;
    const int tx  = tid & 15;   // n
    const int ty  = tid >> 4;   // m
    const int bm  = blockIdx.y * 64;
    const int bn  = blockIdx.x * 64;

    float acc[4][4];
#pragma unroll
    for (int i = 0; i < 4; i++)
#pragma unroll
        for (int j = 0; j < 4; j++) acc[i][j] = 0.f;

    for (int k0 = 0; k0 < K; k0 += 32) {
        // Load A tile 64x32 (transpose into As[k][m])
#pragma unroll
        for (int i = 0; i < 2; i++) {
            int idx = tid + i * 256;        // 0..511
            int r   = idx >> 3;             // row in tile (0..63)
            int c4  = idx & 7;              // float4 col (0..7)
            int gr  = bm + r;
            float4 v = make_float4(0.f, 0.f, 0.f, 0.f);
            if (gr < M) v = *(const float4*)(A + (size_t)gr * K + k0 + c4 * 4);
            if (RELU) {
                v.x = fmaxf(v.x, 0.f); v.y = fmaxf(v.y, 0.f);
                v.z = fmaxf(v.z, 0.f); v.w = fmaxf(v.w, 0.f);
            }
            As[c4 * 4 + 0][r] = v.x;
            As[c4 * 4 + 1][r] = v.y;
            As[c4 * 4 + 2][r] = v.z;
            As[c4 * 4 + 3][r] = v.w;
        }
        // Load B tile 32x64
#pragma unroll
        for (int i = 0; i < 2; i++) {
            int idx = tid + i * 256;
            int r   = idx >> 4;             // 0..31
            int c4  = idx & 15;             // 0..15
            float4 v = *(const float4*)(B + (size_t)(k0 + r) * N + bn + c4 * 4);
            *(float4*)&Bs[r][c4 * 4] = v;
        }
        __syncthreads();

#pragma unroll
        for (int k = 0; k < 32; k++) {
            float4 a = *(const float4*)&As[k][ty * 4];
            float4 b = *(const float4*)&Bs[k][tx * 4];
            acc[0][0] += a.x * b.x; acc[0][1] += a.x * b.y; acc[0][2] += a.x * b.z; acc[0][3] += a.x * b.w;
            acc[1][0] += a.y * b.x; acc[1][1] += a.y * b.y; acc[1][2] += a.y * b.z; acc[1][3] += a.y * b.w;
            acc[2][0] += a.z * b.x; acc[2][1] += a.z * b.y; acc[2][2] += a.z * b.z; acc[2][3] += a.z * b.w;
            acc[3][0] += a.w * b.x; acc[3][1] += a.w * b.y; acc[3][2] += a.w * b.z; acc[3][3] += a.w * b.w;
        }
        __syncthreads();
    }

#pragma unroll
    for (int i = 0; i < 4; i++) {
        int gr = bm + ty * 4 + i;
        if (gr < M) {
            float4 v = make_float4(acc[i][0], acc[i][1], acc[i][2], acc[i][3]);
            *(float4*)(C + (size_t)gr * N + bn + tx * 4) = v;
        }
    }
}

// ---------------------------------------------------------------------------
// Vectorized global reduction: red.global.add.v4.f32 (PTX ISA 8.1, sm_90+)
// ---------------------------------------------------------------------------
__device__ __forceinline__ void red_add_v4(float* addr, float x, float y, float z, float w) {
    asm volatile("red.global.add.v4.f32 [%0], {%1, %2, %3, %4};"
                 :: "l"(addr), "f"(x), "f"(y), "f"(z), "f"(w)
                 : "memory");
}

// SpMM for F=256: one warp per edge. Coalesced 1KB gather of sup[src],
// 2x float4 RED per lane into out[dst].
__global__ __launch_bounds__(256) void spmm_f256(const int* __restrict__ src,
                                                 const int* __restrict__ dst,
                                                 const float* __restrict__ w,
                                                 const float* __restrict__ sup,
                                                 float* __restrict__ out, int E) {
    int gw   = (blockIdx.x * 256 + threadIdx.x) >> 5;
    int lane = threadIdx.x & 31;
    if (gw >= E) return;
    int   s  = __ldg(&src[gw]);
    int   d  = __ldg(&dst[gw]);
    float wt = __ldg(&w[gw]);
    const float4* srow = (const float4*)(sup + (size_t)s * 256);
    float*        drow = out + (size_t)d * 256;
#pragma unroll
    for (int i = 0; i < 2; i++) {
        int c = lane + i * 32;          // float4 index 0..63
        float4 v = srow[c];
        red_add_v4(drow + c * 4, v.x * wt, v.y * wt, v.z * wt, v.w * wt);
    }
}

// SpMM for F=64: 16 threads (one float4 each) per edge.
__global__ __launch_bounds__(256) void spmm_f64(const int* __restrict__ src,
                                                const int* __restrict__ dst,
                                                const float* __restrict__ w,
                                                const float* __restrict__ sup,
                                                float* __restrict__ out, int E) {
    int t  = blockIdx.x * 256 + threadIdx.x;
    int e  = t >> 4;
    int sl = t & 15;
    if (e >= E) return;
    int   s  = __ldg(&src[e]);
    int   d  = __ldg(&dst[e]);
    float wt = __ldg(&w[e]);
    float4 v = ((const float4*)(sup + (size_t)s * 64))[sl];
    red_add_v4(out + (size_t)d * 64 + sl * 4, v.x * wt, v.y * wt, v.z * wt, v.w * wt);
}

// ---------------------------------------------------------------------------
// Row softmax over 64 columns: one warp per row, 2 values per lane.
// ---------------------------------------------------------------------------
__global__ __launch_bounds__(256) void softmax64(const float* __restrict__ in,
                                                 float* __restrict__ out, int M) {
    int row  = (blockIdx.x * 256 + threadIdx.x) >> 5;
    int lane = threadIdx.x & 31;
    if (row >= M) return;
    const float* r = in + (size_t)row * 64;
    float a = r[lane];
    float b = r[lane + 32];
    float m = fmaxf(a, b);
#pragma unroll
    for (int o = 16; o; o >>= 1) m = fmaxf(m, __shfl_xor_sync(0xFFFFFFFFu, m, o));
    float ea = __expf(a - m);
    float eb = __expf(b - m);
    float s  = ea + eb;
#pragma unroll
    for (int o = 16; o; o >>= 1) s += __shfl_xor_sync(0xFFFFFFFFu, s, o);
    float inv = 1.f / s;
    float* orow = out + (size_t)row * 64;
    orow[lane]      = ea * inv;
    orow[lane + 32] = eb * inv;
}

__global__ __launch_bounds__(256) void zero_f4(float4* __restrict__ p, int n4) {
    int i = blockIdx.x * 256 + threadIdx.x;
    if (i < n4) p[i] = make_float4(0.f, 0.f, 0.f, 0.f);
}

// ---------------------------------------------------------------------------
extern "C" void kernel_launch(void* const* d_in, const int* in_sizes, int n_in,
                              void* d_out, int out_size) {
    const float* x  = (const float*)d_in[0];
    const int*   ei = (const int*)d_in[1];
    const float* ew = (const float*)d_in[2];
    const float* W1 = (const float*)d_in[3];
    const float* W2 = (const float*)d_in[4];
    float*       out = (float*)d_out;

    const int E = in_sizes[2];          // 3,200,000
    const int M = in_sizes[0] / IND;    // 100,000
    const int* src = ei;                // row 0 of edge_index
    const int* dst = ei + E;            // row 1

    float *p_sup1, *p_h, *p_sup2, *p_o2;
    cudaGetSymbolAddress((void**)&p_sup1, g_sup1);
    cudaGetSymbolAddress((void**)&p_h,    g_h);
    cudaGetSymbolAddress((void**)&p_sup2, g_sup2);
    cudaGetSymbolAddress((void**)&p_o2,   g_o2);

    const int mtiles = (M + 63) / 64;

    // Layer 1: sup1 = x @ W1
    gemm64<false><<<dim3(HIDD / 64, mtiles), 256>>>(x, W1, p_sup1, M, HIDD, IND);

    // h = 0; h[dst] += w * sup1[src]
    {
        int n4 = M * HIDD / 4;
        zero_f4<<<(n4 + 255) / 256, 256>>>((float4*)p_h, n4);
    }
    spmm_f256<<<(E * 32 + 255) / 256, 256>>>(src, dst, ew, p_sup1, p_h, E);

    // Layer 2: sup2 = relu(h) @ W2
    gemm64<true><<<dim3(OUTD / 64, mtiles), 256>>>(p_h, W2, p_sup2, M, OUTD, HIDD);

    // o2 = 0; o2[dst] += w * sup2[src]
    {
        int n4 = M * OUTD / 4;
        zero_f4<<<(n4 + 255) / 256, 256>>>((float4*)p_o2, n4);
    }
    spmm_f64<<<(E * 16 + 255) / 256, 256>>>(src, dst, ew, p_sup2, p_o2, E);

    // out = softmax(o2, axis=1)
    softmax64<<<(M * 32 + 255) / 256, 256>>>(p_o2, out, M);
}

// round 4
// speedup vs baseline: 1.4342x; 1.4342x over previous
#include <cuda_runtime.h>
#include <cstdint>
#include <cstddef>

#define NN   100000
#define IND  512
#define HIDD 256
#define OUTD 64

// Scratch (device globals: allocation-free, graph-capture safe). ~256 MB.
__device__ float g_sup1[(size_t)NN * HIDD];  // x @ W1
__device__ float g_h   [(size_t)NN * HIDD];  // spmm1 accum
__device__ float g_sup2[(size_t)NN * OUTD];  // relu(h) @ W2
__device__ float g_o2  [(size_t)NN * OUTD];  // spmm2 accum

__device__ __forceinline__ float to_tf32(float x) {
    float r;
    asm("cvt.rna.tf32.f32 %0, %1;" : "=f"(r) : "f"(x));
    return r;
}

// ---------------------------------------------------------------------------
// TF32 tensor-core GEMM: C[M,N] = A[M,K] @ B[K,N], row-major.
// BM=128, BN template (128 or 64), BK=32. 256 threads = 8 warps laid out
// 4 (M) x 2 (N); warp tile 32 x (BN/2); mma.sync.m16n8k8 tf32.
// Optional ReLU applied to A at shared-fill. K, N must divide BK / BN.
// ---------------------------------------------------------------------------
template <int BN, bool RELU>
__global__ __launch_bounds__(256) void gemm_tf32(const float* __restrict__ A,
                                                 const float* __restrict__ B,
                                                 float* __restrict__ C,
                                                 int M, int N, int K) {
    constexpr int BM = 128, BK = 32;
    constexpr int WN = BN / 2;       // warp tile N
    constexpr int NT = WN / 8;       // mma tiles along N per warp

    __shared__ __align__(16) float As[BM][BK + 4];   // pitch 36: banks 4g+t, conflict-free
    __shared__ __align__(16) float Bs[BK][BN + 8];   // pitch BN+8: banks 8t+g, conflict-free

    const int tid  = threadIdx.x;
    const int warp = tid >> 5;
    const int lane = tid & 31;
    const int g    = lane >> 2;      // group id (0..7)
    const int t    = lane & 3;       // thread-in-group (0..3)
    const int wm   = warp & 3;       // warp M index (0..3)
    const int wn   = warp >> 2;      // warp N index (0..1)
    const int bm   = blockIdx.y * BM;
    const int bn   = blockIdx.x * BN;

    float acc[2][NT][4];
#pragma unroll
    for (int mt = 0; mt < 2; mt++)
#pragma unroll
        for (int nt = 0; nt < NT; nt++)
#pragma unroll
            for (int i = 0; i < 4; i++) acc[mt][nt][i] = 0.f;

    for (int k0 = 0; k0 < K; k0 += BK) {
        // ---- load A tile (BM x 32): 1024 float4, 4 per thread ----
#pragma unroll
        for (int i = 0; i < 4; i++) {
            int idx = tid + i * 256;
            int r   = idx >> 3;          // row in tile
            int c4  = idx & 7;           // float4 col
            int gr  = bm + r;
            float4 v = make_float4(0.f, 0.f, 0.f, 0.f);
            if (gr < M) v = *(const float4*)(A + (size_t)gr * K + k0 + c4 * 4);
            if (RELU) {
                v.x = fmaxf(v.x, 0.f); v.y = fmaxf(v.y, 0.f);
                v.z = fmaxf(v.z, 0.f); v.w = fmaxf(v.w, 0.f);
            }
            v.x = to_tf32(v.x); v.y = to_tf32(v.y);
            v.z = to_tf32(v.z); v.w = to_tf32(v.w);
            *(float4*)&As[r][c4 * 4] = v;
        }
        // ---- load B tile (32 x BN): 8*BN float4, BN/32 per thread ----
#pragma unroll
        for (int i = 0; i < BN / 32; i++) {
            int idx = tid + i * 256;
            int r   = idx / (BN / 4);
            int c4  = idx % (BN / 4);
            float4 v = *(const float4*)(B + (size_t)(k0 + r) * N + bn + c4 * 4);
            v.x = to_tf32(v.x); v.y = to_tf32(v.y);
            v.z = to_tf32(v.z); v.w = to_tf32(v.w);
            *(float4*)&Bs[r][c4 * 4] = v;
        }
        __syncthreads();

#pragma unroll
        for (int kk = 0; kk < 4; kk++) {        // 4 x k=8 steps
            unsigned a[2][4], b[NT][2];
#pragma unroll
            for (int mt = 0; mt < 2; mt++) {
                int row = wm * 32 + mt * 16 + g;
                a[mt][0] = __float_as_uint(As[row    ][kk * 8 + t    ]);
                a[mt][1] = __float_as_uint(As[row + 8][kk * 8 + t    ]);
                a[mt][2] = __float_as_uint(As[row    ][kk * 8 + t + 4]);
                a[mt][3] = __float_as_uint(As[row + 8][kk * 8 + t + 4]);
            }
#pragma unroll
            for (int nt = 0; nt < NT; nt++) {
                int col = wn * WN + nt * 8 + g;
                b[nt][0] = __float_as_uint(Bs[kk * 8 + t    ][col]);
                b[nt][1] = __float_as_uint(Bs[kk * 8 + t + 4][col]);
            }
#pragma unroll
            for (int mt = 0; mt < 2; mt++)
#pragma unroll
                for (int nt = 0; nt < NT; nt++) {
                    asm volatile(
                        "mma.sync.aligned.m16n8k8.row.col.f32.tf32.tf32.f32 "
                        "{%0,%1,%2,%3}, {%4,%5,%6,%7}, {%8,%9}, {%0,%1,%2,%3};"
                        : "+f"(acc[mt][nt][0]), "+f"(acc[mt][nt][1]),
                          "+f"(acc[mt][nt][2]), "+f"(acc[mt][nt][3])
                        : "r"(a[mt][0]), "r"(a[mt][1]), "r"(a[mt][2]), "r"(a[mt][3]),
                          "r"(b[nt][0]), "r"(b[nt][1]));
                }
        }
        __syncthreads();
    }

    // ---- store C ----
#pragma unroll
    for (int mt = 0; mt < 2; mt++) {
        int row0 = bm + wm * 32 + mt * 16 + g;
#pragma unroll
        for (int nt = 0; nt < NT; nt++) {
            int col = bn + wn * WN + nt * 8 + t * 2;
            if (row0 < M)
                *(float2*)(C + (size_t)row0 * N + col) =
                    make_float2(acc[mt][nt][0], acc[mt][nt][1]);
            if (row0 + 8 < M)
                *(float2*)(C + (size_t)(row0 + 8) * N + col) =
                    make_float2(acc[mt][nt][2], acc[mt][nt][3]);
        }
    }
}

// ---------------------------------------------------------------------------
// Vectorized global reduction: red.global.add.v4.f32 (sm_90+)
// ---------------------------------------------------------------------------
__device__ __forceinline__ void red_add_v4(float* addr, float x, float y, float z, float w) {
    asm volatile("red.global.add.v4.f32 [%0], {%1, %2, %3, %4};"
                 :: "l"(addr), "f"(x), "f"(y), "f"(z), "f"(w)
                 : "memory");
}

// SpMM for F=256: one warp per edge.
__global__ __launch_bounds__(256) void spmm_f256(const int* __restrict__ src,
                                                 const int* __restrict__ dst,
                                                 const float* __restrict__ w,
                                                 const float* __restrict__ sup,
                                                 float* __restrict__ out, int E) {
    int gw   = (blockIdx.x * 256 + threadIdx.x) >> 5;
    int lane = threadIdx.x & 31;
    if (gw >= E) return;
    int   s  = __ldg(&src[gw]);
    int   d  = __ldg(&dst[gw]);
    float wt = __ldg(&w[gw]);
    const float4* srow = (const float4*)(sup + (size_t)s * 256);
    float*        drow = out + (size_t)d * 256;
#pragma unroll
    for (int i = 0; i < 2; i++) {
        int c = lane + i * 32;
        float4 v = srow[c];
        red_add_v4(drow + c * 4, v.x * wt, v.y * wt, v.z * wt, v.w * wt);
    }
}

// SpMM for F=64: 16 threads (one float4 each) per edge.
__global__ __launch_bounds__(256) void spmm_f64(const int* __restrict__ src,
                                                const int* __restrict__ dst,
                                                const float* __restrict__ w,
                                                const float* __restrict__ sup,
                                                float* __restrict__ out, int E) {
    int t  = blockIdx.x * 256 + threadIdx.x;
    int e  = t >> 4;
    int sl = t & 15;
    if (e >= E) return;
    int   s  = __ldg(&src[e]);
    int   d  = __ldg(&dst[e]);
    float wt = __ldg(&w[e]);
    float4 v = ((const float4*)(sup + (size_t)s * 64))[sl];
    red_add_v4(out + (size_t)d * 64 + sl * 4, v.x * wt, v.y * wt, v.z * wt, v.w * wt);
}

// ---------------------------------------------------------------------------
// Row softmax over 64 columns: one warp per row.
// ---------------------------------------------------------------------------
__global__ __launch_bounds__(256) void softmax64(const float* __restrict__ in,
                                                 float* __restrict__ out, int M) {
    int row  = (blockIdx.x * 256 + threadIdx.x) >> 5;
    int lane = threadIdx.x & 31;
    if (row >= M) return;
    const float* r = in + (size_t)row * 64;
    float a = r[lane];
    float b = r[lane + 32];
    float m = fmaxf(a, b);
#pragma unroll
    for (int o = 16; o; o >>= 1) m = fmaxf(m, __shfl_xor_sync(0xFFFFFFFFu, m, o));
    float ea = __expf(a - m);
    float eb = __expf(b - m);
    float s  = ea + eb;
#pragma unroll
    for (int o = 16; o; o >>= 1) s += __shfl_xor_sync(0xFFFFFFFFu, s, o);
    float inv = 1.f / s;
    float* orow = out + (size_t)row * 64;
    orow[lane]      = ea * inv;
    orow[lane + 32] = eb * inv;
}

__global__ __launch_bounds__(256) void zero_f4(float4* __restrict__ p, int n4) {
    int i = blockIdx.x * 256 + threadIdx.x;
    if (i < n4) p[i] = make_float4(0.f, 0.f, 0.f, 0.f);
}

// ---------------------------------------------------------------------------
extern "C" void kernel_launch(void* const* d_in, const int* in_sizes, int n_in,
                              void* d_out, int out_size) {
    const float* x  = (const float*)d_in[0];
    const int*   ei = (const int*)d_in[1];
    const float* ew = (const float*)d_in[2];
    const float* W1 = (const float*)d_in[3];
    const float* W2 = (const float*)d_in[4];
    float*       out = (float*)d_out;

    const int E = in_sizes[2];          // 3,200,000
    const int M = in_sizes[0] / IND;    // 100,000
    const int* src = ei;                // row 0 of edge_index
    const int* dst = ei + E;            // row 1

    float *p_sup1, *p_h, *p_sup2, *p_o2;
    cudaGetSymbolAddress((void**)&p_sup1, g_sup1);
    cudaGetSymbolAddress((void**)&p_h,    g_h);
    cudaGetSymbolAddress((void**)&p_sup2, g_sup2);
    cudaGetSymbolAddress((void**)&p_o2,   g_o2);

    const int mt128 = (M + 127) / 128;

    // Layer 1: sup1 = x @ W1   (tensor-core TF32)
    gemm_tf32<128, false><<<dim3(HIDD / 128, mt128), 256>>>(x, W1, p_sup1, M, HIDD, IND);

    // h = 0; h[dst] += w * sup1[src]
    {
        int n4 = M * HIDD / 4;
        zero_f4<<<(n4 + 255) / 256, 256>>>((float4*)p_h, n4);
    }
    spmm_f256<<<(E * 32 + 255) / 256, 256>>>(src, dst, ew, p_sup1, p_h, E);

    // Layer 2: sup2 = relu(h) @ W2   (tensor-core TF32, ReLU fused on A)
    gemm_tf32<64, true><<<dim3(OUTD / 64, mt128), 256>>>(p_h, W2, p_sup2, M, OUTD, HIDD);

    // o2 = 0; o2[dst] += w * sup2[src]
    {
        int n4 = M * OUTD / 4;
        zero_f4<<<(n4 + 255) / 256, 256>>>((float4*)p_o2, n4);
    }
    spmm_f64<<<(E * 16 + 255) / 256, 256>>>(src, dst, ew, p_sup2, p_o2, E);

    // out = softmax(o2, axis=1)
    softmax64<<<(M * 32 + 255) / 256, 256>>>(p_o2, out, M);
}

// round 5
// speedup vs baseline: 1.7619x; 1.2285x over previous
#include <cuda_runtime.h>
#include <cstdint>
#include <cstddef>

#define NN   100000
#define IND  512
#define HIDD 256
#define OUTD 64
#define NEDGE_MAX 3400000

// Scratch (device globals: allocation-free, graph-capture safe). ~258 MB.
__device__ float g_sup1[(size_t)NN * HIDD];   // x @ W1
__device__ float g_h   [(size_t)NN * HIDD];   // spmm1 result
__device__ float g_sup2[(size_t)NN * OUTD];   // relu(h) @ W2
__device__ int   g_deg   [NN];
__device__ int   g_rowptr[NN + 1];
__device__ int   g_cursor[NN];
__device__ int2  g_csr   [NEDGE_MAX];         // {src, w-as-int-bits} sorted by dst

__device__ __forceinline__ float to_tf32(float x) {
    float r;
    asm("cvt.rna.tf32.f32 %0, %1;" : "=f"(r) : "f"(x));
    return r;
}

// ---------------------------------------------------------------------------
// TF32 tensor-core GEMM: C[M,N] = A[M,K] @ B[K,N], row-major.
// BM=128, BN template, BK=32, 256 thr = 8 warps (4Mx2N), mma.m16n8k8.tf32.
// ---------------------------------------------------------------------------
template <int BN, bool RELU>
__global__ __launch_bounds__(256) void gemm_tf32(const float* __restrict__ A,
                                                 const float* __restrict__ B,
                                                 float* __restrict__ C,
                                                 int M, int N, int K) {
    constexpr int BM = 128, BK = 32;
    constexpr int WN = BN / 2;
    constexpr int NT = WN / 8;

    __shared__ __align__(16) float As[BM][BK + 4];
    __shared__ __align__(16) float Bs[BK][BN + 8];

    const int tid  = threadIdx.x;
    const int warp = tid >> 5;
    const int lane = tid & 31;
    const int g    = lane >> 2;
    const int t    = lane & 3;
    const int wm   = warp & 3;
    const int wn   = warp >> 2;
    const int bm   = blockIdx.y * BM;
    const int bn   = blockIdx.x * BN;

    float acc[2][NT][4];
#pragma unroll
    for (int mt = 0; mt < 2; mt++)
#pragma unroll
        for (int nt = 0; nt < NT; nt++)
#pragma unroll
            for (int i = 0; i < 4; i++) acc[mt][nt][i] = 0.f;

    for (int k0 = 0; k0 < K; k0 += BK) {
#pragma unroll
        for (int i = 0; i < 4; i++) {
            int idx = tid + i * 256;
            int r   = idx >> 3;
            int c4  = idx & 7;
            int gr  = bm + r;
            float4 v = make_float4(0.f, 0.f, 0.f, 0.f);
            if (gr < M) v = *(const float4*)(A + (size_t)gr * K + k0 + c4 * 4);
            if (RELU) {
                v.x = fmaxf(v.x, 0.f); v.y = fmaxf(v.y, 0.f);
                v.z = fmaxf(v.z, 0.f); v.w = fmaxf(v.w, 0.f);
            }
            v.x = to_tf32(v.x); v.y = to_tf32(v.y);
            v.z = to_tf32(v.z); v.w = to_tf32(v.w);
            *(float4*)&As[r][c4 * 4] = v;
        }
#pragma unroll
        for (int i = 0; i < BN / 32; i++) {
            int idx = tid + i * 256;
            int r   = idx / (BN / 4);
            int c4  = idx % (BN / 4);
            float4 v = *(const float4*)(B + (size_t)(k0 + r) * N + bn + c4 * 4);
            v.x = to_tf32(v.x); v.y = to_tf32(v.y);
            v.z = to_tf32(v.z); v.w = to_tf32(v.w);
            *(float4*)&Bs[r][c4 * 4] = v;
        }
        __syncthreads();

#pragma unroll
        for (int kk = 0; kk < 4; kk++) {
            unsigned a[2][4], b[NT][2];
#pragma unroll
            for (int mt = 0; mt < 2; mt++) {
                int row = wm * 32 + mt * 16 + g;
                a[mt][0] = __float_as_uint(As[row    ][kk * 8 + t    ]);
                a[mt][1] = __float_as_uint(As[row + 8][kk * 8 + t    ]);
                a[mt][2] = __float_as_uint(As[row    ][kk * 8 + t + 4]);
                a[mt][3] = __float_as_uint(As[row + 8][kk * 8 + t + 4]);
            }
#pragma unroll
            for (int nt = 0; nt < NT; nt++) {
                int col = wn * WN + nt * 8 + g;
                b[nt][0] = __float_as_uint(Bs[kk * 8 + t    ][col]);
                b[nt][1] = __float_as_uint(Bs[kk * 8 + t + 4][col]);
            }
#pragma unroll
            for (int mt = 0; mt < 2; mt++)
#pragma unroll
                for (int nt = 0; nt < NT; nt++) {
                    asm volatile(
                        "mma.sync.aligned.m16n8k8.row.col.f32.tf32.tf32.f32 "
                        "{%0,%1,%2,%3}, {%4,%5,%6,%7}, {%8,%9}, {%0,%1,%2,%3};"
                        : "+f"(acc[mt][nt][0]), "+f"(acc[mt][nt][1]),
                          "+f"(acc[mt][nt][2]), "+f"(acc[mt][nt][3])
                        : "r"(a[mt][0]), "r"(a[mt][1]), "r"(a[mt][2]), "r"(a[mt][3]),
                          "r"(b[nt][0]), "r"(b[nt][1]));
                }
        }
        __syncthreads();
    }

#pragma unroll
    for (int mt = 0; mt < 2; mt++) {
        int row0 = bm + wm * 32 + mt * 16 + g;
#pragma unroll
        for (int nt = 0; nt < NT; nt++) {
            int col = bn + wn * WN + nt * 8 + t * 2;
            if (row0 < M)
                *(float2*)(C + (size_t)row0 * N + col) =
                    make_float2(acc[mt][nt][0], acc[mt][nt][1]);
            if (row0 + 8 < M)
                *(float2*)(C + (size_t)(row0 + 8) * N + col) =
                    make_float2(acc[mt][nt][2], acc[mt][nt][3]);
        }
    }
}

// ---------------------------------------------------------------------------
// CSR build: zero -> histogram -> single-block scan -> scatter
// ---------------------------------------------------------------------------
__global__ __launch_bounds__(256) void zero_deg(int* __restrict__ deg, int n) {
    int i = blockIdx.x * 256 + threadIdx.x;
    if (i < n) deg[i] = 0;
}

__global__ __launch_bounds__(256) void hist_dst(const int* __restrict__ dst,
                                                int* __restrict__ deg, int E) {
    int i = blockIdx.x * 256 + threadIdx.x;
    if (i < E) atomicAdd(&deg[dst[i]], 1);
}

__global__ __launch_bounds__(1024) void scan_deg(const int* __restrict__ deg,
                                                 int* __restrict__ rowptr,
                                                 int* __restrict__ cursor, int n) {
    __shared__ int warp_sums[32];
    const int tid  = threadIdx.x;
    const int lane = tid & 31;
    const int wid  = tid >> 5;
    const int per  = (n + 1023) / 1024;
    const int start = tid * per;
    const int end   = min(start + per, n);

    int sum = 0;
    for (int i = start; i < end; i++) sum += deg[i];

    int v = sum;
#pragma unroll
    for (int o = 1; o < 32; o <<= 1) {
        int u = __shfl_up_sync(0xFFFFFFFFu, v, o);
        if (lane >= o) v += u;
    }
    if (lane == 31) warp_sums[wid] = v;
    __syncthreads();
    if (wid == 0) {
        int s = warp_sums[lane];
#pragma unroll
        for (int o = 1; o < 32; o <<= 1) {
            int u = __shfl_up_sync(0xFFFFFFFFu, s, o);
            if (lane >= o) s += u;
        }
        warp_sums[lane] = s;
    }
    __syncthreads();

    int run = v - sum + (wid ? warp_sums[wid - 1] : 0);   // exclusive prefix
    for (int i = start; i < end; i++) {
        rowptr[i] = run;
        cursor[i] = run;
        run += deg[i];
    }
    if (start < n && end == n) rowptr[n] = run;
}

__global__ __launch_bounds__(256) void scatter_edges(const int* __restrict__ src,
                                                     const int* __restrict__ dst,
                                                     const float* __restrict__ w,
                                                     int* __restrict__ cursor,
                                                     int2* __restrict__ csr, int E) {
    int i = blockIdx.x * 256 + threadIdx.x;
    if (i >= E) return;
    int pos = atomicAdd(&cursor[dst[i]], 1);
    csr[pos] = make_int2(src[i], __float_as_int(w[i]));
}

// ---------------------------------------------------------------------------
// CSR SpMM, F=256: one warp per dst row; 8 accum floats/lane; 2-edge unroll.
// ---------------------------------------------------------------------------
__global__ __launch_bounds__(256) void spmm_csr_f256(const int* __restrict__ rowptr,
                                                     const int2* __restrict__ csr,
                                                     const float* __restrict__ sup,
                                                     float* __restrict__ out, int n) {
    int row  = (blockIdx.x * 256 + threadIdx.x) >> 5;
    int lane = threadIdx.x & 31;
    if (row >= n) return;
    int e   = rowptr[row];
    int end = rowptr[row + 1];

    float4 acc0 = make_float4(0.f, 0.f, 0.f, 0.f);
    float4 acc1 = make_float4(0.f, 0.f, 0.f, 0.f);

    for (; e + 2 <= end; e += 2) {
        int2 sw0 = __ldg(&csr[e]);
        int2 sw1 = __ldg(&csr[e + 1]);
        float w0 = __int_as_float(sw0.y);
        float w1 = __int_as_float(sw1.y);
        const float4* r0 = (const float4*)(sup + (size_t)sw0.x * 256);
        const float4* r1 = (const float4*)(sup + (size_t)sw1.x * 256);
        float4 a0 = r0[lane], a1 = r0[lane + 32];
        float4 b0 = r1[lane], b1 = r1[lane + 32];
        acc0.x += w0 * a0.x; acc0.y += w0 * a0.y; acc0.z += w0 * a0.z; acc0.w += w0 * a0.w;
        acc1.x += w0 * a1.x; acc1.y += w0 * a1.y; acc1.z += w0 * a1.z; acc1.w += w0 * a1.w;
        acc0.x += w1 * b0.x; acc0.y += w1 * b0.y; acc0.z += w1 * b0.z; acc0.w += w1 * b0.w;
        acc1.x += w1 * b1.x; acc1.y += w1 * b1.y; acc1.z += w1 * b1.z; acc1.w += w1 * b1.w;
    }
    if (e < end) {
        int2 sw = __ldg(&csr[e]);
        float w = __int_as_float(sw.y);
        const float4* r = (const float4*)(sup + (size_t)sw.x * 256);
        float4 a0 = r[lane], a1 = r[lane + 32];
        acc0.x += w * a0.x; acc0.y += w * a0.y; acc0.z += w * a0.z; acc0.w += w * a0.w;
        acc1.x += w * a1.x; acc1.y += w * a1.y; acc1.z += w * a1.z; acc1.w += w * a1.w;
    }

    float4* orow = (float4*)(out + (size_t)row * 256);
    orow[lane]      = acc0;
    orow[lane + 32] = acc1;
}

// ---------------------------------------------------------------------------
// CSR SpMM, F=64, fused row-softmax: one warp per dst row; float2/lane.
// Writes softmax(row) directly to the output buffer.
// ---------------------------------------------------------------------------
__global__ __launch_bounds__(256) void spmm_csr_f64_softmax(const int* __restrict__ rowptr,
                                                            const int2* __restrict__ csr,
                                                            const float* __restrict__ sup,
                                                            float* __restrict__ out, int n) {
    int row  = (blockIdx.x * 256 + threadIdx.x) >> 5;
    int lane = threadIdx.x & 31;
    if (row >= n) return;
    int e   = rowptr[row];
    int end = rowptr[row + 1];

    float2 acc = make_float2(0.f, 0.f);

    for (; e + 2 <= end; e += 2) {
        int2 sw0 = __ldg(&csr[e]);
        int2 sw1 = __ldg(&csr[e + 1]);
        float w0 = __int_as_float(sw0.y);
        float w1 = __int_as_float(sw1.y);
        float2 v0 = ((const float2*)(sup + (size_t)sw0.x * 64))[lane];
        float2 v1 = ((const float2*)(sup + (size_t)sw1.x * 64))[lane];
        acc.x += w0 * v0.x; acc.y += w0 * v0.y;
        acc.x += w1 * v1.x; acc.y += w1 * v1.y;
    }
    if (e < end) {
        int2 sw = __ldg(&csr[e]);
        float w = __int_as_float(sw.y);
        float2 v = ((const float2*)(sup + (size_t)sw.x * 64))[lane];
        acc.x += w * v.x; acc.y += w * v.y;
    }

    // softmax over the 64 values (2/lane)
    float m = fmaxf(acc.x, acc.y);
#pragma unroll
    for (int o = 16; o; o >>= 1) m = fmaxf(m, __shfl_xor_sync(0xFFFFFFFFu, m, o));
    float ex = __expf(acc.x - m);
    float ey = __expf(acc.y - m);
    float s  = ex + ey;
#pragma unroll
    for (int o = 16; o; o >>= 1) s += __shfl_xor_sync(0xFFFFFFFFu, s, o);
    float inv = 1.f / s;
    ((float2*)(out + (size_t)row * 64))[lane] = make_float2(ex * inv, ey * inv);
}

// ---------------------------------------------------------------------------
extern "C" void kernel_launch(void* const* d_in, const int* in_sizes, int n_in,
                              void* d_out, int out_size) {
    const float* x  = (const float*)d_in[0];
    const int*   ei = (const int*)d_in[1];
    const float* ew = (const float*)d_in[2];
    const float* W1 = (const float*)d_in[3];
    const float* W2 = (const float*)d_in[4];
    float*       out = (float*)d_out;

    const int E = in_sizes[2];
    const int M = in_sizes[0] / IND;
    const int* src = ei;
    const int* dst = ei + E;

    float *p_sup1, *p_h, *p_sup2;
    int *p_deg, *p_rowptr, *p_cursor;
    int2 *p_csr;
    cudaGetSymbolAddress((void**)&p_sup1,   g_sup1);
    cudaGetSymbolAddress((void**)&p_h,      g_h);
    cudaGetSymbolAddress((void**)&p_sup2,   g_sup2);
    cudaGetSymbolAddress((void**)&p_deg,    g_deg);
    cudaGetSymbolAddress((void**)&p_rowptr, g_rowptr);
    cudaGetSymbolAddress((void**)&p_cursor, g_cursor);
    cudaGetSymbolAddress((void**)&p_csr,    g_csr);

    const int eb = (E + 255) / 256;
    const int mb = (M + 255) / 256;
    const int mt128 = (M + 127) / 128;

    // CSR build (dst-sorted adjacency, reused by both layers)
    zero_deg<<<mb, 256>>>(p_deg, M);
    hist_dst<<<eb, 256>>>(dst, p_deg, E);
    scan_deg<<<1, 1024>>>(p_deg, p_rowptr, p_cursor, M);
    scatter_edges<<<eb, 256>>>(src, dst, ew, p_cursor, p_csr, E);

    // Layer 1: sup1 = x @ W1 ; h = A @ sup1
    gemm_tf32<128, false><<<dim3(HIDD / 128, mt128), 256>>>(x, W1, p_sup1, M, HIDD, IND);
    spmm_csr_f256<<<(M * 32 + 255) / 256, 256>>>(p_rowptr, p_csr, p_sup1, p_h, M);

    // Layer 2: sup2 = relu(h) @ W2 ; out = softmax(A @ sup2)
    gemm_tf32<64, true><<<dim3(OUTD / 64, mt128), 256>>>(p_h, W2, p_sup2, M, OUTD, HIDD);
    spmm_csr_f64_softmax<<<(M * 32 + 255) / 256, 256>>>(p_rowptr, p_csr, p_sup2, out, M);
}

// round 6
// speedup vs baseline: 2.8406x; 1.6123x over previous
#include <cuda_runtime.h>
#include <cuda_fp16.h>
#include <cstdint>
#include <cstddef>

#define NN   100000
#define IND  512
#define HIDD 256
#define OUTD 64
#define NEDGE_MAX 3400000

// Scratch (device globals: allocation-free, graph-capture safe). ~210 MB.
__device__ __half g_sup1[(size_t)NN * HIDD]; // x @ W1  (fp16 storage, fp32 math)
__device__ float  g_h   [(size_t)NN * HIDD]; // spmm1 result
__device__ float  g_sup2[(size_t)NN * OUTD]; // relu(h) @ W2
__device__ int    g_deg   [NN];
__device__ int    g_rowptr[NN + 1];
__device__ int    g_cursor[NN];
__device__ int2   g_csr   [NEDGE_MAX];       // {src, w-bits} sorted by dst

__device__ __forceinline__ float to_tf32(float x) {
    float r;
    asm("cvt.rna.tf32.f32 %0, %1;" : "=f"(r) : "f"(x));
    return r;
}

// ---------------------------------------------------------------------------
// TF32 tensor-core GEMM: C[M,N] = A[M,K] @ B[K,N], row-major.
// BM=128, BN template, BK=32, 256 thr = 8 warps (4Mx2N), mma.m16n8k8.tf32.
// HALF_OUT: store C as __half (round-to-nearest).
// ---------------------------------------------------------------------------
template <int BN, bool RELU, bool HALF_OUT>
__global__ __launch_bounds__(256) void gemm_tf32(const float* __restrict__ A,
                                                 const float* __restrict__ B,
                                                 void* __restrict__ Cv,
                                                 int M, int N, int K) {
    constexpr int BM = 128, BK = 32;
    constexpr int WN = BN / 2;
    constexpr int NT = WN / 8;

    __shared__ __align__(16) float As[BM][BK + 4];
    __shared__ __align__(16) float Bs[BK][BN + 8];

    const int tid  = threadIdx.x;
    const int warp = tid >> 5;
    const int lane = tid & 31;
    const int g    = lane >> 2;
    const int t    = lane & 3;
    const int wm   = warp & 3;
    const int wn   = warp >> 2;
    const int bm   = blockIdx.y * BM;
    const int bn   = blockIdx.x * BN;

    float acc[2][NT][4];
#pragma unroll
    for (int mt = 0; mt < 2; mt++)
#pragma unroll
        for (int nt = 0; nt < NT; nt++)
#pragma unroll
            for (int i = 0; i < 4; i++) acc[mt][nt][i] = 0.f;

    for (int k0 = 0; k0 < K; k0 += BK) {
#pragma unroll
        for (int i = 0; i < 4; i++) {
            int idx = tid + i * 256;
            int r   = idx >> 3;
            int c4  = idx & 7;
            int gr  = bm + r;
            float4 v = make_float4(0.f, 0.f, 0.f, 0.f);
            if (gr < M) v = *(const float4*)(A + (size_t)gr * K + k0 + c4 * 4);
            if (RELU) {
                v.x = fmaxf(v.x, 0.f); v.y = fmaxf(v.y, 0.f);
                v.z = fmaxf(v.z, 0.f); v.w = fmaxf(v.w, 0.f);
            }
            v.x = to_tf32(v.x); v.y = to_tf32(v.y);
            v.z = to_tf32(v.z); v.w = to_tf32(v.w);
            *(float4*)&As[r][c4 * 4] = v;
        }
#pragma unroll
        for (int i = 0; i < BN / 32; i++) {
            int idx = tid + i * 256;
            int r   = idx / (BN / 4);
            int c4  = idx % (BN / 4);
            float4 v = *(const float4*)(B + (size_t)(k0 + r) * N + bn + c4 * 4);
            v.x = to_tf32(v.x); v.y = to_tf32(v.y);
            v.z = to_tf32(v.z); v.w = to_tf32(v.w);
            *(float4*)&Bs[r][c4 * 4] = v;
        }
        __syncthreads();

#pragma unroll
        for (int kk = 0; kk < 4; kk++) {
            unsigned a[2][4], b[NT][2];
#pragma unroll
            for (int mt = 0; mt < 2; mt++) {
                int row = wm * 32 + mt * 16 + g;
                a[mt][0] = __float_as_uint(As[row    ][kk * 8 + t    ]);
                a[mt][1] = __float_as_uint(As[row + 8][kk * 8 + t    ]);
                a[mt][2] = __float_as_uint(As[row    ][kk * 8 + t + 4]);
                a[mt][3] = __float_as_uint(As[row + 8][kk * 8 + t + 4]);
            }
#pragma unroll
            for (int nt = 0; nt < NT; nt++) {
                int col = wn * WN + nt * 8 + g;
                b[nt][0] = __float_as_uint(Bs[kk * 8 + t    ][col]);
                b[nt][1] = __float_as_uint(Bs[kk * 8 + t + 4][col]);
            }
#pragma unroll
            for (int mt = 0; mt < 2; mt++)
#pragma unroll
                for (int nt = 0; nt < NT; nt++) {
                    asm volatile(
                        "mma.sync.aligned.m16n8k8.row.col.f32.tf32.tf32.f32 "
                        "{%0,%1,%2,%3}, {%4,%5,%6,%7}, {%8,%9}, {%0,%1,%2,%3};"
                        : "+f"(acc[mt][nt][0]), "+f"(acc[mt][nt][1]),
                          "+f"(acc[mt][nt][2]), "+f"(acc[mt][nt][3])
                        : "r"(a[mt][0]), "r"(a[mt][1]), "r"(a[mt][2]), "r"(a[mt][3]),
                          "r"(b[nt][0]), "r"(b[nt][1]));
                }
        }
        __syncthreads();
    }

#pragma unroll
    for (int mt = 0; mt < 2; mt++) {
        int row0 = bm + wm * 32 + mt * 16 + g;
#pragma unroll
        for (int nt = 0; nt < NT; nt++) {
            int col = bn + wn * WN + nt * 8 + t * 2;
            if (HALF_OUT) {
                __half* C = (__half*)Cv;
                if (row0 < M)
                    *(__half2*)(C + (size_t)row0 * N + col) =
                        __floats2half2_rn(acc[mt][nt][0], acc[mt][nt][1]);
                if (row0 + 8 < M)
                    *(__half2*)(C + (size_t)(row0 + 8) * N + col) =
                        __floats2half2_rn(acc[mt][nt][2], acc[mt][nt][3]);
            } else {
                float* C = (float*)Cv;
                if (row0 < M)
                    *(float2*)(C + (size_t)row0 * N + col) =
                        make_float2(acc[mt][nt][0], acc[mt][nt][1]);
                if (row0 + 8 < M)
                    *(float2*)(C + (size_t)(row0 + 8) * N + col) =
                        make_float2(acc[mt][nt][2], acc[mt][nt][3]);
            }
        }
    }
}

// ---------------------------------------------------------------------------
// CSR build: memset -> histogram(4/thr) -> single-block scan -> scatter(2/thr)
// ---------------------------------------------------------------------------
__global__ __launch_bounds__(256) void hist_dst(const int* __restrict__ dst,
                                                int* __restrict__ deg, int E) {
    int i = (blockIdx.x * 256 + threadIdx.x) * 4;
    if (i + 4 <= E) {
        int4 d = *(const int4*)(dst + i);
        atomicAdd(&deg[d.x], 1);
        atomicAdd(&deg[d.y], 1);
        atomicAdd(&deg[d.z], 1);
        atomicAdd(&deg[d.w], 1);
    } else {
        for (; i < E; i++) atomicAdd(&deg[dst[i]], 1);
    }
}

__global__ __launch_bounds__(1024) void scan_deg(const int* __restrict__ deg,
                                                 int* __restrict__ rowptr,
                                                 int* __restrict__ cursor, int n) {
    __shared__ int warp_sums[32];
    const int tid  = threadIdx.x;
    const int lane = tid & 31;
    const int wid  = tid >> 5;
    const int per  = (n + 1023) / 1024;
    const int start = tid * per;
    const int end   = min(start + per, n);

    int sum = 0;
    for (int i = start; i < end; i++) sum += deg[i];

    int v = sum;
#pragma unroll
    for (int o = 1; o < 32; o <<= 1) {
        int u = __shfl_up_sync(0xFFFFFFFFu, v, o);
        if (lane >= o) v += u;
    }
    if (lane == 31) warp_sums[wid] = v;
    __syncthreads();
    if (wid == 0) {
        int s = warp_sums[lane];
#pragma unroll
        for (int o = 1; o < 32; o <<= 1) {
            int u = __shfl_up_sync(0xFFFFFFFFu, s, o);
            if (lane >= o) s += u;
        }
        warp_sums[lane] = s;
    }
    __syncthreads();

    int run = v - sum + (wid ? warp_sums[wid - 1] : 0);
    for (int i = start; i < end; i++) {
        rowptr[i] = run;
        cursor[i] = run;
        run += deg[i];
    }
    if (start < n && end == n) rowptr[n] = run;
}

__global__ __launch_bounds__(256) void scatter_edges(const int* __restrict__ src,
                                                     const int* __restrict__ dst,
                                                     const float* __restrict__ w,
                                                     int* __restrict__ cursor,
                                                     int2* __restrict__ csr, int E) {
    int i = (blockIdx.x * 256 + threadIdx.x) * 2;
    if (i + 2 <= E) {
        int2   s2 = *(const int2*)(src + i);
        int2   d2 = *(const int2*)(dst + i);
        float2 w2 = *(const float2*)(w + i);
        int p0 = atomicAdd(&cursor[d2.x], 1);
        int p1 = atomicAdd(&cursor[d2.y], 1);
        csr[p0] = make_int2(s2.x, __float_as_int(w2.x));
        csr[p1] = make_int2(s2.y, __float_as_int(w2.y));
    } else {
        for (; i < E; i++) {
            int pos = atomicAdd(&cursor[dst[i]], 1);
            csr[pos] = make_int2(src[i], __float_as_int(w[i]));
        }
    }
}

// ---------------------------------------------------------------------------
// CSR SpMM, F=256, fp16 gather / fp32 accum: one warp per dst row.
// Each lane reads one uint4 (8 halves) per edge; 8 fp32 accumulators/lane.
// ---------------------------------------------------------------------------
__global__ __launch_bounds__(256) void spmm_csr_f256h(const int* __restrict__ rowptr,
                                                      const int2* __restrict__ csr,
                                                      const __half* __restrict__ sup,
                                                      float* __restrict__ out, int n) {
    int row  = (blockIdx.x * 256 + threadIdx.x) >> 5;
    int lane = threadIdx.x & 31;
    if (row >= n) return;
    int e   = rowptr[row];
    int end = rowptr[row + 1];

    float acc[8];
#pragma unroll
    for (int i = 0; i < 8; i++) acc[i] = 0.f;

    for (; e + 2 <= end; e += 2) {
        int2 sw0 = __ldg(&csr[e]);
        int2 sw1 = __ldg(&csr[e + 1]);
        float w0 = __int_as_float(sw0.y);
        float w1 = __int_as_float(sw1.y);
        uint4 v0 = ((const uint4*)(sup + (size_t)sw0.x * 256))[lane];
        uint4 v1 = ((const uint4*)(sup + (size_t)sw1.x * 256))[lane];
        const __half2* h0 = (const __half2*)&v0;
        const __half2* h1 = (const __half2*)&v1;
#pragma unroll
        for (int j = 0; j < 4; j++) {
            float2 f0 = __half22float2(h0[j]);
            float2 f1 = __half22float2(h1[j]);
            acc[2 * j]     += w0 * f0.x + w1 * f1.x;
            acc[2 * j + 1] += w0 * f0.y + w1 * f1.y;
        }
    }
    if (e < end) {
        int2 sw = __ldg(&csr[e]);
        float w = __int_as_float(sw.y);
        uint4 v = ((const uint4*)(sup + (size_t)sw.x * 256))[lane];
        const __half2* h = (const __half2*)&v;
#pragma unroll
        for (int j = 0; j < 4; j++) {
            float2 f = __half22float2(h[j]);
            acc[2 * j]     += w * f.x;
            acc[2 * j + 1] += w * f.y;
        }
    }

    float4* orow = (float4*)(out + (size_t)row * 256 + lane * 8);
    orow[0] = make_float4(acc[0], acc[1], acc[2], acc[3]);
    orow[1] = make_float4(acc[4], acc[5], acc[6], acc[7]);
}

// ---------------------------------------------------------------------------
// CSR SpMM, F=64 (fp32), fused row-softmax: one warp per dst row.
// ---------------------------------------------------------------------------
__global__ __launch_bounds__(256) void spmm_csr_f64_softmax(const int* __restrict__ rowptr,
                                                            const int2* __restrict__ csr,
                                                            const float* __restrict__ sup,
                                                            float* __restrict__ out, int n) {
    int row  = (blockIdx.x * 256 + threadIdx.x) >> 5;
    int lane = threadIdx.x & 31;
    if (row >= n) return;
    int e   = rowptr[row];
    int end = rowptr[row + 1];

    float2 acc = make_float2(0.f, 0.f);

    for (; e + 2 <= end; e += 2) {
        int2 sw0 = __ldg(&csr[e]);
        int2 sw1 = __ldg(&csr[e + 1]);
        float w0 = __int_as_float(sw0.y);
        float w1 = __int_as_float(sw1.y);
        float2 v0 = ((const float2*)(sup + (size_t)sw0.x * 64))[lane];
        float2 v1 = ((const float2*)(sup + (size_t)sw1.x * 64))[lane];
        acc.x += w0 * v0.x + w1 * v1.x;
        acc.y += w0 * v0.y + w1 * v1.y;
    }
    if (e < end) {
        int2 sw = __ldg(&csr[e]);
        float w = __int_as_float(sw.y);
        float2 v = ((const float2*)(sup + (size_t)sw.x * 64))[lane];
        acc.x += w * v.x;
        acc.y += w * v.y;
    }

    float m = fmaxf(acc.x, acc.y);
#pragma unroll
    for (int o = 16; o; o >>= 1) m = fmaxf(m, __shfl_xor_sync(0xFFFFFFFFu, m, o));
    float ex = __expf(acc.x - m);
    float ey = __expf(acc.y - m);
    float s  = ex + ey;
#pragma unroll
    for (int o = 16; o; o >>= 1) s += __shfl_xor_sync(0xFFFFFFFFu, s, o);
    float inv = 1.f / s;
    ((float2*)(out + (size_t)row * 64))[lane] = make_float2(ex * inv, ey * inv);
}

// ---------------------------------------------------------------------------
extern "C" void kernel_launch(void* const* d_in, const int* in_sizes, int n_in,
                              void* d_out, int out_size) {
    const float* x  = (const float*)d_in[0];
    const int*   ei = (const int*)d_in[1];
    const float* ew = (const float*)d_in[2];
    const float* W1 = (const float*)d_in[3];
    const float* W2 = (const float*)d_in[4];
    float*       out = (float*)d_out;

    const int E = in_sizes[2];
    const int M = in_sizes[0] / IND;
    const int* src = ei;
    const int* dst = ei + E;

    __half* p_sup1;
    float *p_h, *p_sup2;
    int *p_deg, *p_rowptr, *p_cursor;
    int2 *p_csr;
    cudaGetSymbolAddress((void**)&p_sup1,   g_sup1);
    cudaGetSymbolAddress((void**)&p_h,      g_h);
    cudaGetSymbolAddress((void**)&p_sup2,   g_sup2);
    cudaGetSymbolAddress((void**)&p_deg,    g_deg);
    cudaGetSymbolAddress((void**)&p_rowptr, g_rowptr);
    cudaGetSymbolAddress((void**)&p_cursor, g_cursor);
    cudaGetSymbolAddress((void**)&p_csr,    g_csr);

    const int mt128 = (M + 127) / 128;

    // CSR build (dst-sorted adjacency, reused by both layers)
    cudaMemsetAsync(p_deg, 0, (size_t)M * sizeof(int));
    hist_dst<<<(E / 4 + 255) / 256, 256>>>(dst, p_deg, E);
    scan_deg<<<1, 1024>>>(p_deg, p_rowptr, p_cursor, M);
    scatter_edges<<<(E / 2 + 255) / 256, 256>>>(src, dst, ew, p_cursor, p_csr, E);

    // Layer 1: sup1 = fp16(x @ W1) ; h = A @ sup1
    gemm_tf32<128, false, true><<<dim3(HIDD / 128, mt128), 256>>>(x, W1, p_sup1, M, HIDD, IND);
    spmm_csr_f256h<<<(M * 32 + 255) / 256, 256>>>(p_rowptr, p_csr, p_sup1, p_h, M);

    // Layer 2: sup2 = relu(h) @ W2 ; out = softmax(A @ sup2)
    gemm_tf32<64, true, false><<<dim3(OUTD / 64, mt128), 256>>>(p_h, W2, p_sup2, M, OUTD, HIDD);
    spmm_csr_f64_softmax<<<(M * 32 + 255) / 256, 256>>>(p_rowptr, p_csr, p_sup2, out, M);
}